// round 2
// baseline (speedup 1.0000x reference)
#include <cuda_runtime.h>

#define B_ 32
#define L_ 1024
#define D_ 1024

#define BM 128
#define BN 128
#define BK 8
#define NTHREADS 256

// 128 MB scratch for the attention matrix (scores, then alpha in place).
// Referenced directly from device code — no host-side symbol lookup needed.
__device__ float g_alpha[(size_t)B_ * L_ * L_];

// ---------------------------------------------------------------------------
// Kernel 1: S[b,r,c] = (r==c || mask[b,c]==0) ? 0 : dot(x[b,r,:], x[b,c,:])
// Classic 128x128x8 fp32 SGEMM tile, 8x8 per thread (split 4+4 pattern).
// ---------------------------------------------------------------------------
__global__ __launch_bounds__(NTHREADS) void scores_kernel(
    const float* __restrict__ x, const int* __restrict__ xmask)
{
    const int b = blockIdx.z;
    const float* X = x + (size_t)b * L_ * D_;
    float* S = g_alpha + (size_t)b * L_ * L_;
    const int* mrow = xmask + b * L_;

    const int rowBase = blockIdx.y * BM;
    const int colBase = blockIdx.x * BN;

    __shared__ float As[BK][BM];
    __shared__ float Bs[BK][BN];

    const int tid = threadIdx.x;
    const int loadRow = tid >> 1;          // 0..127
    const int loadSeg = (tid & 1) * 4;     // 0 or 4

    const int tx = tid & 15;               // 0..15
    const int ty = tid >> 4;               // 0..15

    float acc[8][8];
#pragma unroll
    for (int i = 0; i < 8; i++)
#pragma unroll
        for (int j = 0; j < 8; j++) acc[i][j] = 0.f;

    for (int k0 = 0; k0 < D_; k0 += BK) {
        float4 a4 = *(const float4*)(X + (size_t)(rowBase + loadRow) * D_ + k0 + loadSeg);
        float4 b4 = *(const float4*)(X + (size_t)(colBase + loadRow) * D_ + k0 + loadSeg);
        __syncthreads();
        As[loadSeg + 0][loadRow] = a4.x; As[loadSeg + 1][loadRow] = a4.y;
        As[loadSeg + 2][loadRow] = a4.z; As[loadSeg + 3][loadRow] = a4.w;
        Bs[loadSeg + 0][loadRow] = b4.x; Bs[loadSeg + 1][loadRow] = b4.y;
        Bs[loadSeg + 2][loadRow] = b4.z; Bs[loadSeg + 3][loadRow] = b4.w;
        __syncthreads();
#pragma unroll
        for (int k = 0; k < BK; k++) {
            float ar[8], br[8];
            float4 a0 = *(const float4*)&As[k][ty * 4];
            float4 a1 = *(const float4*)&As[k][ty * 4 + 64];
            float4 b0 = *(const float4*)&Bs[k][tx * 4];
            float4 b1 = *(const float4*)&Bs[k][tx * 4 + 64];
            ar[0]=a0.x; ar[1]=a0.y; ar[2]=a0.z; ar[3]=a0.w;
            ar[4]=a1.x; ar[5]=a1.y; ar[6]=a1.z; ar[7]=a1.w;
            br[0]=b0.x; br[1]=b0.y; br[2]=b0.z; br[3]=b0.w;
            br[4]=b1.x; br[5]=b1.y; br[6]=b1.z; br[7]=b1.w;
#pragma unroll
            for (int i = 0; i < 8; i++)
#pragma unroll
                for (int j = 0; j < 8; j++) acc[i][j] = fmaf(ar[i], br[j], acc[i][j]);
        }
    }

#pragma unroll
    for (int i = 0; i < 8; i++) {
        int r = rowBase + ty * 4 + (i < 4 ? i : 60 + i);   // ty*4+i  or  ty*4+64+(i-4)
#pragma unroll
        for (int j = 0; j < 8; j++) {
            int c = colBase + tx * 4 + (j < 4 ? j : 60 + j);
            float v = acc[i][j];
            if (r == c || mrow[c] == 0) v = 0.f;
            S[(size_t)r * L_ + c] = v;
        }
    }
}

// ---------------------------------------------------------------------------
// Kernel 2: in-place row softmax-renormalize.
// alpha_m = exp(s_m - max) * mask_m / (S_masked + 1e-13 * Z_full)
// (max / Z_full computed over ALL columns incl. zeros, matching reference)
// ---------------------------------------------------------------------------
__global__ __launch_bounds__(256) void softmax_kernel(const int* __restrict__ xmask)
{
    const int row = blockIdx.x;        // 0..B*L-1
    const int b = row >> 10;
    float* srow = g_alpha + (size_t)row * L_;
    const int* mrow = xmask + b * L_;
    const int tid = threadIdx.x;

    float4 v = *(const float4*)(srow + tid * 4);
    int4 mk = *(const int4*)(mrow + tid * 4);

    __shared__ float red[8];

    // --- block max ---
    float mx = fmaxf(fmaxf(v.x, v.y), fmaxf(v.z, v.w));
#pragma unroll
    for (int o = 16; o > 0; o >>= 1) mx = fmaxf(mx, __shfl_xor_sync(0xffffffffu, mx, o));
    if ((tid & 31) == 0) red[tid >> 5] = mx;
    __syncthreads();
    if (tid < 32) {
        float t = (tid < 8) ? red[tid] : -3.4e38f;
#pragma unroll
        for (int o = 4; o > 0; o >>= 1) t = fmaxf(t, __shfl_xor_sync(0xffffffffu, t, o));
        if (tid == 0) red[0] = t;
    }
    __syncthreads();
    mx = red[0];
    __syncthreads();

    // --- exps + two sums (full and masked) ---
    float e0 = __expf(v.x - mx), e1 = __expf(v.y - mx);
    float e2 = __expf(v.z - mx), e3 = __expf(v.w - mx);
    float m0 = (mk.x != 0) ? 1.f : 0.f, m1 = (mk.y != 0) ? 1.f : 0.f;
    float m2 = (mk.z != 0) ? 1.f : 0.f, m3 = (mk.w != 0) ? 1.f : 0.f;
    float zf = e0 + e1 + e2 + e3;
    float sm = e0 * m0 + e1 * m1 + e2 * m2 + e3 * m3;

    float2 s2 = make_float2(zf, sm);
#pragma unroll
    for (int o = 16; o > 0; o >>= 1) {
        s2.x += __shfl_xor_sync(0xffffffffu, s2.x, o);
        s2.y += __shfl_xor_sync(0xffffffffu, s2.y, o);
    }
    __shared__ float redz[8], redm[8];
    if ((tid & 31) == 0) { redz[tid >> 5] = s2.x; redm[tid >> 5] = s2.y; }
    __syncthreads();
    if (tid < 32) {
        float tz = (tid < 8) ? redz[tid] : 0.f;
        float tm = (tid < 8) ? redm[tid] : 0.f;
#pragma unroll
        for (int o = 4; o > 0; o >>= 1) {
            tz += __shfl_xor_sync(0xffffffffu, tz, o);
            tm += __shfl_xor_sync(0xffffffffu, tm, o);
        }
        if (tid == 0) { redz[0] = tz; redm[0] = tm; }
    }
    __syncthreads();
    const float inv = 1.f / (redm[0] + 1e-13f * redz[0]);

    float4 o4;
    o4.x = e0 * m0 * inv; o4.y = e1 * m1 * inv;
    o4.z = e2 * m2 * inv; o4.w = e3 * m3 * inv;
    *(float4*)(srow + tid * 4) = o4;
}

// ---------------------------------------------------------------------------
// Kernel 3: O[b] = alpha[b] @ X[b]   (NN GEMM, M=L, N=D, K=L)
// ---------------------------------------------------------------------------
__global__ __launch_bounds__(NTHREADS) void out_kernel(
    const float* __restrict__ x, float* __restrict__ out)
{
    const int b = blockIdx.z;
    const float* A = g_alpha + (size_t)b * L_ * L_;
    const float* X = x + (size_t)b * L_ * D_;
    float* O = out + (size_t)b * L_ * D_;

    const int rowBase = blockIdx.y * BM;
    const int colBase = blockIdx.x * BN;

    __shared__ float As[BK][BM];
    __shared__ float Bs[BK][BN];

    const int tid = threadIdx.x;
    const int aRow = tid >> 1;
    const int aSeg = (tid & 1) * 4;
    const int bRow = tid >> 5;            // 0..7
    const int bCol = (tid & 31) * 4;      // 0..124

    const int tx = tid & 15;
    const int ty = tid >> 4;

    float acc[8][8];
#pragma unroll
    for (int i = 0; i < 8; i++)
#pragma unroll
        for (int j = 0; j < 8; j++) acc[i][j] = 0.f;

    for (int k0 = 0; k0 < L_; k0 += BK) {
        float4 a4 = *(const float4*)(A + (size_t)(rowBase + aRow) * L_ + k0 + aSeg);
        float4 b4 = *(const float4*)(X + (size_t)(k0 + bRow) * D_ + colBase + bCol);
        __syncthreads();
        As[aSeg + 0][aRow] = a4.x; As[aSeg + 1][aRow] = a4.y;
        As[aSeg + 2][aRow] = a4.z; As[aSeg + 3][aRow] = a4.w;
        *(float4*)&Bs[bRow][bCol] = b4;
        __syncthreads();
#pragma unroll
        for (int k = 0; k < BK; k++) {
            float ar[8], br[8];
            float4 a0 = *(const float4*)&As[k][ty * 4];
            float4 a1 = *(const float4*)&As[k][ty * 4 + 64];
            float4 b0 = *(const float4*)&Bs[k][tx * 4];
            float4 b1 = *(const float4*)&Bs[k][tx * 4 + 64];
            ar[0]=a0.x; ar[1]=a0.y; ar[2]=a0.z; ar[3]=a0.w;
            ar[4]=a1.x; ar[5]=a1.y; ar[6]=a1.z; ar[7]=a1.w;
            br[0]=b0.x; br[1]=b0.y; br[2]=b0.z; br[3]=b0.w;
            br[4]=b1.x; br[5]=b1.y; br[6]=b1.z; br[7]=b1.w;
#pragma unroll
            for (int i = 0; i < 8; i++)
#pragma unroll
                for (int j = 0; j < 8; j++) acc[i][j] = fmaf(ar[i], br[j], acc[i][j]);
        }
    }

#pragma unroll
    for (int i = 0; i < 8; i++) {
        int r = rowBase + ty * 4 + (i < 4 ? i : 60 + i);
#pragma unroll
        for (int j = 0; j < 8; j++) {
            int c = colBase + tx * 4 + (j < 4 ? j : 60 + j);
            O[(size_t)r * D_ + c] = acc[i][j];
        }
    }
}

extern "C" void kernel_launch(void* const* d_in, const int* in_sizes, int n_in,
                              void* d_out, int out_size)
{
    const float* x = (const float*)d_in[0];
    const int* xmask = (const int*)d_in[1];
    float* out = (float*)d_out;

    dim3 blk(NTHREADS);
    dim3 grid1(L_ / BN, L_ / BM, B_);
    scores_kernel<<<grid1, blk>>>(x, xmask);

    softmax_kernel<<<B_ * L_, 256>>>(xmask);

    dim3 grid3(D_ / BN, L_ / BM, B_);
    out_kernel<<<grid3, blk>>>(x, out);
}

// round 5
// speedup vs baseline: 1.9885x; 1.9885x over previous
#include <cuda_runtime.h>
#include <cuda_bf16.h>
#include <cstdint>

#define B_ 32
#define L_ 1024
#define D_ 1024
typedef __nv_bfloat16 bf16;

// ---------------------------------------------------------------------------
// Scratch (device globals; no allocation in kernel_launch)
// ---------------------------------------------------------------------------
__device__ bf16  g_xh [(size_t)B_ * L_ * D_];   // x hi split, [b, l, d]
__device__ bf16  g_xl [(size_t)B_ * L_ * D_];   // x lo split
__device__ bf16  g_xth[(size_t)B_ * L_ * D_];   // x^T hi, [b, d, l]
__device__ bf16  g_xtl[(size_t)B_ * L_ * D_];   // x^T lo
__device__ float g_scores[(size_t)B_ * L_ * L_];
__device__ bf16  g_ah [(size_t)B_ * L_ * L_];   // alpha hi
__device__ bf16  g_al [(size_t)B_ * L_ * L_];   // alpha lo

// ---------------------------------------------------------------------------
// PTX helpers (baseline ISA only — no tcgen05; harness targets plain sm_103)
// ---------------------------------------------------------------------------
__device__ __forceinline__ uint32_t smem_u32(const void* p) {
    uint32_t a;
    asm("{ .reg .u64 t; cvta.to.shared.u64 t, %1; cvt.u32.u64 %0, t; }" : "=r"(a) : "l"(p));
    return a;
}
#define CP_COMMIT() asm volatile("cp.async.commit_group;" ::: "memory")
#define CP_WAIT1()  asm volatile("cp.async.wait_group 1;" ::: "memory")
#define CP_WAIT0()  asm volatile("cp.async.wait_group 0;" ::: "memory")

__device__ __forceinline__ void cp16(uint32_t dst, const void* src) {
    asm volatile("cp.async.cg.shared.global [%0], [%1], 16;" :: "r"(dst), "l"(src));
}
__device__ __forceinline__ void ldsm4(uint32_t* r, uint32_t addr) {
    asm volatile("ldmatrix.sync.aligned.m8n8.x4.shared.b16 {%0,%1,%2,%3}, [%4];"
                 : "=r"(r[0]), "=r"(r[1]), "=r"(r[2]), "=r"(r[3]) : "r"(addr));
}
__device__ __forceinline__ void mma16816(float* c, const uint32_t* a, const uint32_t* b) {
    asm volatile(
        "mma.sync.aligned.m16n8k16.row.col.f32.bf16.bf16.f32 "
        "{%0,%1,%2,%3}, {%4,%5,%6,%7}, {%8,%9}, {%0,%1,%2,%3};"
        : "+f"(c[0]), "+f"(c[1]), "+f"(c[2]), "+f"(c[3])
        : "r"(a[0]), "r"(a[1]), "r"(a[2]), "r"(a[3]), "r"(b[0]), "r"(b[1]));
}

// ---------------------------------------------------------------------------
// Kernel 0: split x into bf16 hi/lo, plus transposed copies.
// grid (32, 32, B), block (32, 8)
// ---------------------------------------------------------------------------
__global__ __launch_bounds__(256) void conv_kernel(const float* __restrict__ x)
{
    __shared__ bf16 sh[32][33];
    __shared__ bf16 sl[32][33];
    const int b = blockIdx.z;
    const int d0 = blockIdx.x * 32, l0 = blockIdx.y * 32;
    const int tx = threadIdx.x, ty = threadIdx.y;
    const float* X = x + (size_t)b * L_ * D_;
    const size_t bo = (size_t)b * L_ * D_;

#pragma unroll
    for (int i = 0; i < 4; i++) {
        int row = ty + i * 8;
        float v = X[(size_t)(l0 + row) * D_ + d0 + tx];
        bf16 h = __float2bfloat16(v);
        bf16 l = __float2bfloat16(v - __bfloat162float(h));
        size_t o = bo + (size_t)(l0 + row) * D_ + d0 + tx;
        g_xh[o] = h; g_xl[o] = l;
        sh[row][tx] = h; sl[row][tx] = l;
    }
    __syncthreads();
#pragma unroll
    for (int i = 0; i < 4; i++) {
        int row = ty + i * 8;
        size_t o = bo + (size_t)(d0 + row) * L_ + l0 + tx;
        g_xth[o] = sh[tx][row];
        g_xtl[o] = sl[tx][row];
    }
}

// ---------------------------------------------------------------------------
// Split-bf16 HMMA GEMM: 128x128 CTA tile, 8 warps (64x32 warptile),
// mma.sync m16n8k16, KC=32 double-buffered cp.async stages.
// Smem tiles stored with 40-element (80B) row stride — conflict-free ldmatrix.
// SCORES=true : A=B=x splits, out=g_scores with diag/mask zeroing.
// SCORES=false: A=alpha splits, B=x^T splits, out=d_out.
// ---------------------------------------------------------------------------
#define KC 32
#define TROW 40                         // elements per smem row (80 bytes)
#define TILE_BYTES (128 * TROW * 2)     // 10240
#define STAGE_BYTES (4 * TILE_BYTES)    // 40960: Ah, Al, Bh, Bl
#define SMEM_GEMM (2 * STAGE_BYTES)     // 81920

__device__ __forceinline__ void fill_tile(uint32_t dst, const bf16* __restrict__ src,
                                          int rowBase, int k0, int tid)
{
#pragma unroll
    for (int i = 0; i < 2; i++) {
        int idx = i * 256 + tid;          // 0..511
        int row = idx >> 2, seg = idx & 3;
        cp16(dst + row * 80 + seg * 16,
             src + (size_t)(rowBase + row) * 1024 + k0 + seg * 8);
    }
}

template <bool SCORES>
__global__ __launch_bounds__(256, 1) void gemm_kernel(const int* __restrict__ xmask,
                                                      float* __restrict__ gout)
{
    extern __shared__ char smem[];
    const uint32_t sb = smem_u32(smem);
    const int tid = threadIdx.x;
    const int wid = tid >> 5, lane = tid & 31;
    const int wr = wid >> 2, wc = wid & 3;          // 2x4 warp grid
    const int b = blockIdx.z;
    const int rowBase = blockIdx.y * 128;
    const int colBase = blockIdx.x * 128;

    const bf16 *Ah, *Al, *Bh, *Bl;
    float* O;
    const size_t bo = (size_t)b * 1024 * 1024;
    if (SCORES) {
        Ah = g_xh + bo; Al = g_xl + bo; Bh = g_xh + bo; Bl = g_xl + bo;
        O = g_scores + bo;
    } else {
        Ah = g_ah + bo; Al = g_al + bo; Bh = g_xth + bo; Bl = g_xtl + bo;
        O = gout + bo;
    }

    float acc[4][4][4];
#pragma unroll
    for (int i = 0; i < 4; i++)
#pragma unroll
        for (int j = 0; j < 4; j++)
#pragma unroll
            for (int k = 0; k < 4; k++) acc[i][j][k] = 0.f;

    // ldmatrix per-lane address components
    const uint32_t aRowOff = (uint32_t)(wr * 64 + (lane & 15)) * 80;   // + mf*16*80
    const uint32_t aColSel = (uint32_t)(lane >> 4) * 8;                // element offset
    const uint32_t bRowBase = (uint32_t)(wc * 32 + ((lane >> 4) << 3) + (lane & 7)); // + n2*16
    const uint32_t bColSel = (uint32_t)((lane >> 3) & 1) * 8;

    // prologue: fill both stages
#pragma unroll
    for (int s = 0; s < 2; s++) {
        uint32_t st = sb + s * STAGE_BYTES;
        fill_tile(st + 0 * TILE_BYTES, Ah, rowBase, s * KC, tid);
        fill_tile(st + 1 * TILE_BYTES, Al, rowBase, s * KC, tid);
        fill_tile(st + 2 * TILE_BYTES, Bh, colBase, s * KC, tid);
        fill_tile(st + 3 * TILE_BYTES, Bl, colBase, s * KC, tid);
        CP_COMMIT();
    }

    for (int c = 0; c < 32; c++) {
        if (c >= 30) CP_WAIT0(); else CP_WAIT1();
        __syncthreads();
        const uint32_t st = sb + (c & 1) * STAGE_BYTES;

#pragma unroll
        for (int kk = 0; kk < KC; kk += 16) {
            uint32_t ah[4][4], al[4][4], bh[2][4], bl[2][4];
#pragma unroll
            for (int mf = 0; mf < 4; mf++) {
                uint32_t off = aRowOff + (uint32_t)mf * (16 * 80) + (kk + aColSel) * 2;
                ldsm4(ah[mf], st + 0 * TILE_BYTES + off);
                ldsm4(al[mf], st + 1 * TILE_BYTES + off);
            }
#pragma unroll
            for (int n2 = 0; n2 < 2; n2++) {
                uint32_t off = (bRowBase + (uint32_t)n2 * 16) * 80 + (kk + bColSel) * 2;
                ldsm4(bh[n2], st + 2 * TILE_BYTES + off);
                ldsm4(bl[n2], st + 3 * TILE_BYTES + off);
            }
#pragma unroll
            for (int mf = 0; mf < 4; mf++) {
#pragma unroll
                for (int nf = 0; nf < 4; nf++) {
                    const uint32_t* bhp = &bh[nf >> 1][(nf & 1) * 2];
                    const uint32_t* blp = &bl[nf >> 1][(nf & 1) * 2];
                    mma16816(acc[mf][nf], ah[mf], bhp);
                    mma16816(acc[mf][nf], al[mf], bhp);
                    mma16816(acc[mf][nf], ah[mf], blp);
                }
            }
        }
        __syncthreads();
        if (c + 2 < 32) {
            const int k0 = (c + 2) * KC;
            fill_tile(st + 0 * TILE_BYTES, Ah, rowBase, k0, tid);
            fill_tile(st + 1 * TILE_BYTES, Al, rowBase, k0, tid);
            fill_tile(st + 2 * TILE_BYTES, Bh, colBase, k0, tid);
            fill_tile(st + 3 * TILE_BYTES, Bl, colBase, k0, tid);
            CP_COMMIT();
        }
    }

    // epilogue
    const int rb = rowBase + wr * 64 + (lane >> 2);
    const int cb = colBase + wc * 32 + (lane & 3) * 2;
    const int* mrow = SCORES ? (xmask + b * L_) : nullptr;

#pragma unroll
    for (int mf = 0; mf < 4; mf++) {
        const int r = rb + mf * 16;
#pragma unroll
        for (int nf = 0; nf < 4; nf++) {
            const int cc = cb + nf * 8;
            float v0 = acc[mf][nf][0], v1 = acc[mf][nf][1];   // row r,   cols cc, cc+1
            float v2 = acc[mf][nf][2], v3 = acc[mf][nf][3];   // row r+8, cols cc, cc+1
            if (SCORES) {
                const int m0 = mrow[cc], m1 = mrow[cc + 1];
                if (r == cc || m0 == 0) v0 = 0.f;
                if (r == cc + 1 || m1 == 0) v1 = 0.f;
                if (r + 8 == cc || m0 == 0) v2 = 0.f;
                if (r + 8 == cc + 1 || m1 == 0) v3 = 0.f;
            }
            *(float2*)(O + (size_t)r * 1024 + cc) = make_float2(v0, v1);
            *(float2*)(O + (size_t)(r + 8) * 1024 + cc) = make_float2(v2, v3);
        }
    }
}

// ---------------------------------------------------------------------------
// Softmax-renormalize: reads g_scores, writes alpha as bf16 hi/lo splits.
// alpha_m = exp(s_m - max)*mask_m / (S_masked + 1e-13 * Z_full)
// ---------------------------------------------------------------------------
__global__ __launch_bounds__(256) void softmax_kernel(const int* __restrict__ xmask)
{
    const int row = blockIdx.x;
    const int b = row >> 10;
    const float* srow = g_scores + (size_t)row * L_;
    const int* mrow = xmask + b * L_;
    const int tid = threadIdx.x;

    float4 v = *(const float4*)(srow + tid * 4);
    int4 mk = *(const int4*)(mrow + tid * 4);

    __shared__ float red[8];
    float mx = fmaxf(fmaxf(v.x, v.y), fmaxf(v.z, v.w));
#pragma unroll
    for (int o = 16; o > 0; o >>= 1) mx = fmaxf(mx, __shfl_xor_sync(0xffffffffu, mx, o));
    if ((tid & 31) == 0) red[tid >> 5] = mx;
    __syncthreads();
    if (tid < 32) {
        float t = (tid < 8) ? red[tid] : -3.4e38f;
#pragma unroll
        for (int o = 4; o > 0; o >>= 1) t = fmaxf(t, __shfl_xor_sync(0xffffffffu, t, o));
        if (tid == 0) red[0] = t;
    }
    __syncthreads();
    mx = red[0];
    __syncthreads();

    float e0 = __expf(v.x - mx), e1 = __expf(v.y - mx);
    float e2 = __expf(v.z - mx), e3 = __expf(v.w - mx);
    float m0 = (mk.x != 0) ? 1.f : 0.f, m1 = (mk.y != 0) ? 1.f : 0.f;
    float m2 = (mk.z != 0) ? 1.f : 0.f, m3 = (mk.w != 0) ? 1.f : 0.f;
    float zf = e0 + e1 + e2 + e3;
    float sm = e0 * m0 + e1 * m1 + e2 * m2 + e3 * m3;

    float2 s2 = make_float2(zf, sm);
#pragma unroll
    for (int o = 16; o > 0; o >>= 1) {
        s2.x += __shfl_xor_sync(0xffffffffu, s2.x, o);
        s2.y += __shfl_xor_sync(0xffffffffu, s2.y, o);
    }
    __shared__ float redz[8], redm[8];
    if ((tid & 31) == 0) { redz[tid >> 5] = s2.x; redm[tid >> 5] = s2.y; }
    __syncthreads();
    if (tid < 32) {
        float tz = (tid < 8) ? redz[tid] : 0.f;
        float tm = (tid < 8) ? redm[tid] : 0.f;
#pragma unroll
        for (int o = 4; o > 0; o >>= 1) {
            tz += __shfl_xor_sync(0xffffffffu, tz, o);
            tm += __shfl_xor_sync(0xffffffffu, tm, o);
        }
        if (tid == 0) { redz[0] = tz; redm[0] = tm; }
    }
    __syncthreads();
    const float inv = 1.f / (redm[0] + 1e-13f * redz[0]);

    float a[4];
    a[0] = e0 * m0 * inv; a[1] = e1 * m1 * inv;
    a[2] = e2 * m2 * inv; a[3] = e3 * m3 * inv;

    const size_t o = (size_t)row * L_ + tid * 4;
    bf16 hh[4], ll[4];
#pragma unroll
    for (int i = 0; i < 4; i++) {
        hh[i] = __float2bfloat16(a[i]);
        ll[i] = __float2bfloat16(a[i] - __bfloat162float(hh[i]));
    }
    *(uint2*)(g_ah + o) = *(uint2*)hh;
    *(uint2*)(g_al + o) = *(uint2*)ll;
}

// ---------------------------------------------------------------------------
extern "C" void kernel_launch(void* const* d_in, const int* in_sizes, int n_in,
                              void* d_out, int out_size)
{
    const float* x = (const float*)d_in[0];
    const int* xmask = (const int*)d_in[1];
    float* out = (float*)d_out;

    cudaFuncSetAttribute(gemm_kernel<true>,
                         cudaFuncAttributeMaxDynamicSharedMemorySize, SMEM_GEMM);
    cudaFuncSetAttribute(gemm_kernel<false>,
                         cudaFuncAttributeMaxDynamicSharedMemorySize, SMEM_GEMM);

    conv_kernel<<<dim3(32, 32, B_), dim3(32, 8)>>>(x);

    gemm_kernel<true><<<dim3(8, 8, B_), 256, SMEM_GEMM>>>(xmask, nullptr);

    softmax_kernel<<<B_ * L_, 256>>>(xmask);

    gemm_kernel<false><<<dim3(8, 8, B_), 256, SMEM_GEMM>>>(xmask, out);
}

// round 6
// speedup vs baseline: 2.3967x; 1.2052x over previous
#include <cuda_runtime.h>
#include <cuda_bf16.h>
#include <cstdint>

#define B_ 32
#define L_ 1024
#define D_ 1024
typedef __nv_bfloat16 bf16;

// ---------------------------------------------------------------------------
// Scratch (device globals; no allocation in kernel_launch)
// ---------------------------------------------------------------------------
__device__ bf16  g_xh [(size_t)B_ * L_ * D_];   // x hi split, [b, l, d]
__device__ bf16  g_xl [(size_t)B_ * L_ * D_];   // x lo split
__device__ bf16  g_xth[(size_t)B_ * L_ * D_];   // x^T hi, [b, d, l]
__device__ bf16  g_xtl[(size_t)B_ * L_ * D_];   // x^T lo
__device__ float g_scores[(size_t)B_ * L_ * L_];
__device__ bf16  g_ah [(size_t)B_ * L_ * L_];   // alpha hi
__device__ bf16  g_al [(size_t)B_ * L_ * L_];   // alpha lo

// ---------------------------------------------------------------------------
// PTX helpers (baseline ISA only — harness targets plain sm_103, no tcgen05)
// ---------------------------------------------------------------------------
__device__ __forceinline__ uint32_t smem_u32(const void* p) {
    uint32_t a;
    asm("{ .reg .u64 t; cvta.to.shared.u64 t, %1; cvt.u32.u64 %0, t; }" : "=r"(a) : "l"(p));
    return a;
}
#define CP_COMMIT() asm volatile("cp.async.commit_group;" ::: "memory")
#define CP_WAIT1()  asm volatile("cp.async.wait_group 1;" ::: "memory")
#define CP_WAIT0()  asm volatile("cp.async.wait_group 0;" ::: "memory")

__device__ __forceinline__ void cp16(uint32_t dst, const void* src) {
    asm volatile("cp.async.cg.shared.global [%0], [%1], 16;" :: "r"(dst), "l"(src));
}
__device__ __forceinline__ void ldsm4(uint32_t* r, uint32_t addr) {
    asm volatile("ldmatrix.sync.aligned.m8n8.x4.shared.b16 {%0,%1,%2,%3}, [%4];"
                 : "=r"(r[0]), "=r"(r[1]), "=r"(r[2]), "=r"(r[3]) : "r"(addr));
}
__device__ __forceinline__ void mma16816(float* c, const uint32_t* a, const uint32_t* b) {
    asm volatile(
        "mma.sync.aligned.m16n8k16.row.col.f32.bf16.bf16.f32 "
        "{%0,%1,%2,%3}, {%4,%5,%6,%7}, {%8,%9}, {%0,%1,%2,%3};"
        : "+f"(c[0]), "+f"(c[1]), "+f"(c[2]), "+f"(c[3])
        : "r"(a[0]), "r"(a[1]), "r"(a[2]), "r"(a[3]), "r"(b[0]), "r"(b[1]));
}

// ---------------------------------------------------------------------------
// Kernel 0: split x into bf16 hi/lo, plus transposed copies.
// ---------------------------------------------------------------------------
__global__ __launch_bounds__(256) void conv_kernel(const float* __restrict__ x)
{
    __shared__ bf16 sh[32][33];
    __shared__ bf16 sl[32][33];
    const int b = blockIdx.z;
    const int d0 = blockIdx.x * 32, l0 = blockIdx.y * 32;
    const int tx = threadIdx.x, ty = threadIdx.y;
    const float* X = x + (size_t)b * L_ * D_;
    const size_t bo = (size_t)b * L_ * D_;

#pragma unroll
    for (int i = 0; i < 4; i++) {
        int row = ty + i * 8;
        float v = X[(size_t)(l0 + row) * D_ + d0 + tx];
        bf16 h = __float2bfloat16(v);
        bf16 l = __float2bfloat16(v - __bfloat162float(h));
        size_t o = bo + (size_t)(l0 + row) * D_ + d0 + tx;
        g_xh[o] = h; g_xl[o] = l;
        sh[row][tx] = h; sl[row][tx] = l;
    }
    __syncthreads();
#pragma unroll
    for (int i = 0; i < 4; i++) {
        int row = ty + i * 8;
        size_t o = bo + (size_t)(d0 + row) * L_ + l0 + tx;
        g_xth[o] = sh[tx][row];
        g_xtl[o] = sl[tx][row];
    }
}

// ---------------------------------------------------------------------------
// Split-bf16 HMMA GEMM: 128x128 CTA tile, 8 warps (64x32 warptile),
// mma.sync m16n8k16, KC=32 double-buffered cp.async stages.
// __launch_bounds__(256, 2): 2 CTAs/SM (regs<=128) to fill the tensor pipe.
// ---------------------------------------------------------------------------
#define KC 32
#define TROW 40                         // elements per smem row (80 bytes)
#define TILE_BYTES (128 * TROW * 2)     // 10240
#define STAGE_BYTES (4 * TILE_BYTES)    // 40960: Ah, Al, Bh, Bl
#define SMEM_GEMM (2 * STAGE_BYTES)     // 81920; x2 CTAs = 160KB <= 228KB

__device__ __forceinline__ void fill_tile(uint32_t dst, const bf16* __restrict__ src,
                                          int rowBase, int k0, int tid)
{
#pragma unroll
    for (int i = 0; i < 2; i++) {
        int idx = i * 256 + tid;          // 0..511
        int row = idx >> 2, seg = idx & 3;
        cp16(dst + row * 80 + seg * 16,
             src + (size_t)(rowBase + row) * 1024 + k0 + seg * 8);
    }
}

template <bool SCORES>
__global__ __launch_bounds__(256, 2) void gemm_kernel(const int* __restrict__ xmask,
                                                      float* __restrict__ gout)
{
    extern __shared__ char smem[];
    const uint32_t sb = smem_u32(smem);
    const int tid = threadIdx.x;
    const int wid = tid >> 5, lane = tid & 31;
    const int wr = wid >> 2, wc = wid & 3;          // 2x4 warp grid
    const int b = blockIdx.z;
    const int rowBase = blockIdx.y * 128;
    const int colBase = blockIdx.x * 128;

    const bf16 *Ah, *Al, *Bh, *Bl;
    float* O;
    const size_t bo = (size_t)b * 1024 * 1024;
    if (SCORES) {
        Ah = g_xh + bo; Al = g_xl + bo; Bh = g_xh + bo; Bl = g_xl + bo;
        O = g_scores + bo;
    } else {
        Ah = g_ah + bo; Al = g_al + bo; Bh = g_xth + bo; Bl = g_xtl + bo;
        O = gout + bo;
    }

    float acc[4][4][4];
#pragma unroll
    for (int i = 0; i < 4; i++)
#pragma unroll
        for (int j = 0; j < 4; j++)
#pragma unroll
            for (int k = 0; k < 4; k++) acc[i][j][k] = 0.f;

    // ldmatrix per-lane address components
    const uint32_t aRowOff = (uint32_t)(wr * 64 + (lane & 15)) * 80;   // + mf*16*80
    const uint32_t aColSel = (uint32_t)(lane >> 4) * 8;                // element offset
    const uint32_t bRowBase = (uint32_t)(wc * 32 + ((lane >> 4) << 3) + (lane & 7)); // + n2*16
    const uint32_t bColSel = (uint32_t)((lane >> 3) & 1) * 8;

    // prologue: fill both stages
#pragma unroll
    for (int s = 0; s < 2; s++) {
        uint32_t st = sb + s * STAGE_BYTES;
        fill_tile(st + 0 * TILE_BYTES, Ah, rowBase, s * KC, tid);
        fill_tile(st + 1 * TILE_BYTES, Al, rowBase, s * KC, tid);
        fill_tile(st + 2 * TILE_BYTES, Bh, colBase, s * KC, tid);
        fill_tile(st + 3 * TILE_BYTES, Bl, colBase, s * KC, tid);
        CP_COMMIT();
    }

    for (int c = 0; c < 32; c++) {
        if (c >= 30) CP_WAIT0(); else CP_WAIT1();
        __syncthreads();
        const uint32_t st = sb + (c & 1) * STAGE_BYTES;

#pragma unroll
        for (int kk = 0; kk < KC; kk += 16) {
            // B fragments for this k-16 step (16 regs live)
            uint32_t bh[2][4], bl[2][4];
#pragma unroll
            for (int n2 = 0; n2 < 2; n2++) {
                uint32_t off = (bRowBase + (uint32_t)n2 * 16) * 80 + (kk + bColSel) * 2;
                ldsm4(bh[n2], st + 2 * TILE_BYTES + off);
                ldsm4(bl[n2], st + 3 * TILE_BYTES + off);
            }
            // Stream A fragments (8 regs live at a time)
#pragma unroll
            for (int mf = 0; mf < 4; mf++) {
                uint32_t ah[4], al[4];
                uint32_t off = aRowOff + (uint32_t)mf * (16 * 80) + (kk + aColSel) * 2;
                ldsm4(ah, st + 0 * TILE_BYTES + off);
                ldsm4(al, st + 1 * TILE_BYTES + off);
#pragma unroll
                for (int nf = 0; nf < 4; nf++) {
                    const uint32_t* bhp = &bh[nf >> 1][(nf & 1) * 2];
                    const uint32_t* blp = &bl[nf >> 1][(nf & 1) * 2];
                    mma16816(acc[mf][nf], ah, bhp);
                    mma16816(acc[mf][nf], al, bhp);
                    mma16816(acc[mf][nf], ah, blp);
                }
            }
        }
        __syncthreads();
        if (c + 2 < 32) {
            const int k0 = (c + 2) * KC;
            fill_tile(st + 0 * TILE_BYTES, Ah, rowBase, k0, tid);
            fill_tile(st + 1 * TILE_BYTES, Al, rowBase, k0, tid);
            fill_tile(st + 2 * TILE_BYTES, Bh, colBase, k0, tid);
            fill_tile(st + 3 * TILE_BYTES, Bl, colBase, k0, tid);
            CP_COMMIT();
        }
    }

    // epilogue
    const int rb = rowBase + wr * 64 + (lane >> 2);
    const int cb = colBase + wc * 32 + (lane & 3) * 2;
    const int* mrow = SCORES ? (xmask + b * L_) : nullptr;

#pragma unroll
    for (int mf = 0; mf < 4; mf++) {
        const int r = rb + mf * 16;
#pragma unroll
        for (int nf = 0; nf < 4; nf++) {
            const int cc = cb + nf * 8;
            float v0 = acc[mf][nf][0], v1 = acc[mf][nf][1];   // row r,   cols cc, cc+1
            float v2 = acc[mf][nf][2], v3 = acc[mf][nf][3];   // row r+8, cols cc, cc+1
            if (SCORES) {
                const int m0 = mrow[cc], m1 = mrow[cc + 1];
                if (r == cc || m0 == 0) v0 = 0.f;
                if (r == cc + 1 || m1 == 0) v1 = 0.f;
                if (r + 8 == cc || m0 == 0) v2 = 0.f;
                if (r + 8 == cc + 1 || m1 == 0) v3 = 0.f;
            }
            *(float2*)(O + (size_t)r * 1024 + cc) = make_float2(v0, v1);
            *(float2*)(O + (size_t)(r + 8) * 1024 + cc) = make_float2(v2, v3);
        }
    }
}

// ---------------------------------------------------------------------------
// Softmax-renormalize: reads g_scores, writes alpha as bf16 hi/lo splits.
// ---------------------------------------------------------------------------
__global__ __launch_bounds__(256) void softmax_kernel(const int* __restrict__ xmask)
{
    const int row = blockIdx.x;
    const int b = row >> 10;
    const float* srow = g_scores + (size_t)row * L_;
    const int* mrow = xmask + b * L_;
    const int tid = threadIdx.x;

    float4 v = *(const float4*)(srow + tid * 4);
    int4 mk = *(const int4*)(mrow + tid * 4);

    __shared__ float red[8];
    float mx = fmaxf(fmaxf(v.x, v.y), fmaxf(v.z, v.w));
#pragma unroll
    for (int o = 16; o > 0; o >>= 1) mx = fmaxf(mx, __shfl_xor_sync(0xffffffffu, mx, o));
    if ((tid & 31) == 0) red[tid >> 5] = mx;
    __syncthreads();
    if (tid < 32) {
        float t = (tid < 8) ? red[tid] : -3.4e38f;
#pragma unroll
        for (int o = 4; o > 0; o >>= 1) t = fmaxf(t, __shfl_xor_sync(0xffffffffu, t, o));
        if (tid == 0) red[0] = t;
    }
    __syncthreads();
    mx = red[0];
    __syncthreads();

    float e0 = __expf(v.x - mx), e1 = __expf(v.y - mx);
    float e2 = __expf(v.z - mx), e3 = __expf(v.w - mx);
    float m0 = (mk.x != 0) ? 1.f : 0.f, m1 = (mk.y != 0) ? 1.f : 0.f;
    float m2 = (mk.z != 0) ? 1.f : 0.f, m3 = (mk.w != 0) ? 1.f : 0.f;
    float zf = e0 + e1 + e2 + e3;
    float sm = e0 * m0 + e1 * m1 + e2 * m2 + e3 * m3;

    float2 s2 = make_float2(zf, sm);
#pragma unroll
    for (int o = 16; o > 0; o >>= 1) {
        s2.x += __shfl_xor_sync(0xffffffffu, s2.x, o);
        s2.y += __shfl_xor_sync(0xffffffffu, s2.y, o);
    }
    __shared__ float redz[8], redm[8];
    if ((tid & 31) == 0) { redz[tid >> 5] = s2.x; redm[tid >> 5] = s2.y; }
    __syncthreads();
    if (tid < 32) {
        float tz = (tid < 8) ? redz[tid] : 0.f;
        float tm = (tid < 8) ? redm[tid] : 0.f;
#pragma unroll
        for (int o = 4; o > 0; o >>= 1) {
            tz += __shfl_xor_sync(0xffffffffu, tz, o);
            tm += __shfl_xor_sync(0xffffffffu, tm, o);
        }
        if (tid == 0) { redz[0] = tz; redm[0] = tm; }
    }
    __syncthreads();
    const float inv = 1.f / (redm[0] + 1e-13f * redz[0]);

    float a[4];
    a[0] = e0 * m0 * inv; a[1] = e1 * m1 * inv;
    a[2] = e2 * m2 * inv; a[3] = e3 * m3 * inv;

    const size_t o = (size_t)row * L_ + tid * 4;
    bf16 hh[4], ll[4];
#pragma unroll
    for (int i = 0; i < 4; i++) {
        hh[i] = __float2bfloat16(a[i]);
        ll[i] = __float2bfloat16(a[i] - __bfloat162float(hh[i]));
    }
    *(uint2*)(g_ah + o) = *(uint2*)hh;
    *(uint2*)(g_al + o) = *(uint2*)ll;
}

// ---------------------------------------------------------------------------
extern "C" void kernel_launch(void* const* d_in, const int* in_sizes, int n_in,
                              void* d_out, int out_size)
{
    const float* x = (const float*)d_in[0];
    const int* xmask = (const int*)d_in[1];
    float* out = (float*)d_out;

    cudaFuncSetAttribute(gemm_kernel<true>,
                         cudaFuncAttributeMaxDynamicSharedMemorySize, SMEM_GEMM);
    cudaFuncSetAttribute(gemm_kernel<false>,
                         cudaFuncAttributeMaxDynamicSharedMemorySize, SMEM_GEMM);

    conv_kernel<<<dim3(32, 32, B_), dim3(32, 8)>>>(x);

    gemm_kernel<true><<<dim3(8, 8, B_), 256, SMEM_GEMM>>>(xmask, nullptr);

    softmax_kernel<<<B_ * L_, 256>>>(xmask);

    gemm_kernel<false><<<dim3(8, 8, B_), 256, SMEM_GEMM>>>(xmask, out);
}